// round 14
// baseline (speedup 1.0000x reference)
#include <cuda_runtime.h>

#define N 512
#define BATCH 256
#define TPB 256
#define GRIDP 740                   // 5 blocks/SM x 148 SMs -> one wave
#define PROJ_TPB 128

#define F4_ROW       ((N * N) / 4)  // 65536 float4 per batch row
#define CH_F4        2048           // float4 per chunk (32 KB)
#define CH_PER_ROW   (F4_ROW / CH_F4)        // 32
#define TOTAL_CH     (BATCH * CH_PER_ROW)    // 8192
#define CH_ITERS     (CH_F4 / TPB)           // 8

// Scratch (no device allocs allowed)
__device__ __align__(16) float g_u[N];
__device__ __align__(16) float g_v[N];
__device__ float g_partial2[BATCH][CH_PER_ROW];
__device__ int g_done_cnt = 0;

// ---------------------------------------------------------------------------
// Kernel A: u[k] = sum_i wh[i]*cu(i)*cos((2k+1) i pi/(2N)); same for v.
// One block per k, deterministic tree. cospif arg exact (<2^24 numerator).
// ---------------------------------------------------------------------------
__global__ void __launch_bounds__(PROJ_TPB)
proj_kernel(const float* __restrict__ wh, const float* __restrict__ wv) {
    const int k = blockIdx.x;
    const int t = threadIdx.x;

    const float c0 = sqrtf(1.0f / N);
    const float c1 = sqrtf(2.0f / N);
    const float two_k_p1 = (float)(2 * k + 1);

    float su = 0.f, sv = 0.f;
    #pragma unroll
    for (int r = 0; r < N / PROJ_TPB; ++r) {
        int i = r * PROJ_TPB + t;
        float cu = (i == 0) ? c0 : c1;
        float tt = two_k_p1 * (float)i * (1.0f / (2.0f * N));
        float c = cospif(tt) * cu;
        su = fmaf(wh[i], c, su);
        sv = fmaf(wv[i], c, sv);
    }

    __shared__ float ru[PROJ_TPB / 32], rv[PROJ_TPB / 32];
    #pragma unroll
    for (int o = 16; o > 0; o >>= 1) {
        su += __shfl_down_sync(0xffffffffu, su, o);
        sv += __shfl_down_sync(0xffffffffu, sv, o);
    }
    if ((t & 31) == 0) { ru[t >> 5] = su; rv[t >> 5] = sv; }
    __syncthreads();
    if (t == 0) {
        g_u[k] = ru[0] + ru[1] + ru[2] + ru[3];
        g_v[k] = rv[0] + rv[1] + rv[2] + rv[3];
    }
}

// ---------------------------------------------------------------------------
// Kernel B: PERSISTENT streaming reduction. 740 blocks, one wave; each block
// owns a contiguous range of 32KB chunks (~11 each, tail <= 1 chunk).
// Chunk ch: b = ch/32, c = ch%32. For f = i*TPB + t:
//   v index: (t&127)*4 (per-thread constant, hoisted once per block)
//   u index: c*16 + 2i + (t>>7) (broadcast scalar per iter, L1 hit)
// MLP=4 front-batched LDG.128 groups (R11 config). Deterministic slots.
// ---------------------------------------------------------------------------
__global__ void __launch_bounds__(TPB, 5)
reduce_kernel(const float* __restrict__ x,
              const float* __restrict__ bias,
              float* __restrict__ out) {
    const int bid = blockIdx.x;
    const int t   = threadIdx.x;

    const int start = (bid * TOTAL_CH) / GRIDP;
    const int end   = ((bid + 1) * TOTAL_CH) / GRIDP;

    const float4* __restrict__ x4 = reinterpret_cast<const float4*>(x);
    const float4 v4 = *reinterpret_cast<const float4*>(&g_v[(t & 127) * 4]);
    const int ksub = (t >> 7);                       // 0 or 1

    __shared__ float red[TPB / 32];
    __shared__ bool  is_last;

    for (int ch = start; ch < end; ++ch) {
        const int b = ch >> 5;                       // /CH_PER_ROW
        const int c = ch & (CH_PER_ROW - 1);
        const float4* __restrict__ xr = x4 + (size_t)b * F4_ROW + c * CH_F4;
        const float* __restrict__ up = g_u + c * 16 + ksub;

        float acc0 = 0.f, acc1 = 0.f;
        #pragma unroll
        for (int g = 0; g < CH_ITERS; g += 4) {
            float4 x0 = __ldg(xr + (g + 0) * TPB + t);
            float4 x1 = __ldg(xr + (g + 1) * TPB + t);
            float4 x2 = __ldg(xr + (g + 2) * TPB + t);
            float4 x3 = __ldg(xr + (g + 3) * TPB + t);

            float d0 = fmaf(x0.x, v4.x, fmaf(x0.y, v4.y, fmaf(x0.z, v4.z, x0.w * v4.w)));
            float d1 = fmaf(x1.x, v4.x, fmaf(x1.y, v4.y, fmaf(x1.z, v4.z, x1.w * v4.w)));
            float d2 = fmaf(x2.x, v4.x, fmaf(x2.y, v4.y, fmaf(x2.z, v4.z, x2.w * v4.w)));
            float d3 = fmaf(x3.x, v4.x, fmaf(x3.y, v4.y, fmaf(x3.z, v4.z, x3.w * v4.w)));

            acc0 = fmaf(up[2 * (g + 0)], d0, acc0);
            acc1 = fmaf(up[2 * (g + 1)], d1, acc1);
            acc0 = fmaf(up[2 * (g + 2)], d2, acc0);
            acc1 = fmaf(up[2 * (g + 3)], d3, acc1);
        }
        float acc = acc0 + acc1;

        // deterministic block reduction for this chunk
        #pragma unroll
        for (int o = 16; o > 0; o >>= 1)
            acc += __shfl_down_sync(0xffffffffu, acc, o);
        if ((t & 31) == 0) red[t >> 5] = acc;
        __syncthreads();
        if (t == 0) {
            float s = 0.f;
            #pragma unroll
            for (int w = 0; w < TPB / 32; ++w) s += red[w];
            g_partial2[b][c] = s;
        }
        __syncthreads();                             // protect red[] reuse
    }

    // fused finish: last block computes sigmoids in fixed order
    __threadfence();
    if (t == 0) {
        int old = atomicAdd(&g_done_cnt, 1);
        is_last = (old == GRIDP - 1);
    }
    __syncthreads();
    if (is_last) {
        __threadfence();                             // see all partials
        float r = bias[0];
        #pragma unroll
        for (int cc = 0; cc < CH_PER_ROW; ++cc) r += g_partial2[t][cc];
        out[t] = 1.0f / (1.0f + __expf(-r));
        if (t == 0) g_done_cnt = 0;                  // reset for graph replay
    }
}

extern "C" void kernel_launch(void* const* d_in, const int* in_sizes, int n_in,
                              void* d_out, int out_size) {
    const float* x    = (const float*)d_in[0];
    const float* wh   = (const float*)d_in[1];
    const float* wv   = (const float*)d_in[2];
    const float* bias = (const float*)d_in[3];
    float* out = (float*)d_out;

    proj_kernel<<<N, PROJ_TPB>>>(wh, wv);
    reduce_kernel<<<GRIDP, TPB>>>(x, bias, out);
}